// round 13
// baseline (speedup 1.0000x reference)
#include <cuda_runtime.h>
#include <math.h>

constexpr int Bn   = 64;
constexpr int Hn   = 512;
constexpr int Wn   = 512;
constexpr int NPTS = 512;
constexpr int HWn  = Hn * Wn;
constexpr int SLICES = 16;                  // blocks per image
constexpr int RB = Bn * SLICES;             // 1024 blocks (single wave)
constexpr int TAPS_PER_IMG = NPTS * 9;      // 4608
constexpr int TAPS_PER_BLK = TAPS_PER_IMG / SLICES;   // 288
constexpr int NTAP = Bn * TAPS_PER_IMG;     // 294912
constexpr int CB = NTAP / 256;              // 1152 cleanup blocks (per tap)
constexpr float SCALE = 0.25f;              // 512/2048
constexpr double CELL_AREA = 16.0;

// zero-initialized device scratch; restored every call for graph replay
__device__ float  g_target[(size_t)Bn * HWn];
__device__ double g_S[Bn], g_Q[Bn], g_T[Bn], g_A[Bn], g_C[Bn];

// K1: proven R7/R12 kernel + early PDL trigger after the scatter phase.
__global__ void __launch_bounds__(256, 7)
k_main(const float* __restrict__ pred, const float* __restrict__ points) {
    const int tid = threadIdx.x;
    const int b = blockIdx.x >> 4;
    const int slice = blockIdx.x & (SLICES - 1);

    constexpr int CH = HWn / 4 / SLICES;    // 4096 float4 per block
    const float4* p = reinterpret_cast<const float4*>(pred)
                      + (size_t)b * (HWn / 4) + (size_t)slice * CH;
    float s = 0.f, q = 0.f;
    #pragma unroll
    for (int it = 0; it < 2; ++it) {
        float4 v[8];
        #pragma unroll
        for (int j = 0; j < 8; ++j)
            v[j] = p[(it * 8 + j) * 256 + tid];
        #pragma unroll
        for (int j = 0; j < 8; ++j) {
            s += (v[j].x + v[j].y) + (v[j].z + v[j].w);
            q += v[j].x * v[j].x + v[j].y * v[j].y
               + v[j].z * v[j].z + v[j].w * v[j].w;
        }
    }

    float tw = 0.f, ta = 0.f, tc = 0.f;
    const float* pb = pred + (size_t)b * HWn;
    float* tg = g_target + (size_t)b * HWn;
    for (int i = tid; i < TAPS_PER_BLK; i += 256) {
        int tapid = slice * TAPS_PER_BLK + i;    // < 4608
        int pt  = tapid / 9;
        int tap = tapid - pt * 9;
        float px = __ldg(&points[((size_t)b * NPTS + pt) * 2 + 0]);
        float py = __ldg(&points[((size_t)b * NPTS + pt) * 2 + 1]);
        int x = (int)fminf(fmaxf(px * SCALE, 0.f), (float)(Wn - 1));
        int y = (int)fminf(fmaxf(py * SCALE, 0.f), (float)(Hn - 1));
        int dy = tap / 3 - 1;
        int dx = tap - (tap / 3) * 3 - 1;
        int ny = y + dy, nx = x + dx;
        if ((unsigned)ny < (unsigned)Hn && (unsigned)nx < (unsigned)Wn) {
            int r2 = dy * dy + dx * dx;
            float w = (r2 == 0) ? 1.0f : (r2 == 1 ? 0.60653066f : 0.49306869f);
            int idx = ny * Wn + nx;
            float old = atomicAdd(&tg[idx], w);
            tc += w * (2.f * old + w);            // (old+w)^2 - old^2
            ta += w * __ldg(&pb[idx]);
            tw += w;
        }
    }

    // allow tail grid to launch ASAP (gridsync still enforces visibility)
    cudaTriggerProgrammaticLaunchCompletion();

    #pragma unroll
    for (int o = 16; o; o >>= 1) {
        s  += __shfl_down_sync(0xffffffffu, s,  o);
        q  += __shfl_down_sync(0xffffffffu, q,  o);
        tw += __shfl_down_sync(0xffffffffu, tw, o);
        ta += __shfl_down_sync(0xffffffffu, ta, o);
        tc += __shfl_down_sync(0xffffffffu, tc, o);
    }
    __shared__ float sh[5][8];
    int lane = tid & 31, wid = tid >> 5;
    if (lane == 0) {
        sh[0][wid] = s; sh[1][wid] = q; sh[2][wid] = tw;
        sh[3][wid] = ta; sh[4][wid] = tc;
    }
    __syncthreads();
    if (tid == 0) {
        float S = 0.f, Q = 0.f, Tw = 0.f, Ta = 0.f, Tc = 0.f;
        #pragma unroll
        for (int j = 0; j < 8; ++j) {
            S += sh[0][j]; Q += sh[1][j]; Tw += sh[2][j];
            Ta += sh[3][j]; Tc += sh[4][j];
        }
        atomicAdd(&g_S[b], (double)S);
        atomicAdd(&g_Q[b], (double)Q);
        atomicAdd(&g_T[b], (double)Tw);
        atomicAdd(&g_A[b], (double)Ta);
        atomicAdd(&g_C[b], (double)Tc);
    }
}

// K2 (PDL): per-TAP cleanup — prologue decodes everything, gridsync, then
// exactly one store per thread. Finalize block does the scalar math.
__global__ void __launch_bounds__(256)
k_tail(const float* __restrict__ points, float* __restrict__ out) {
    const int tid = threadIdx.x;
    if (blockIdx.x < CB) {
        // ---- independent prologue: full tap decode ----
        int u = blockIdx.x * 256 + tid;
        int pt  = u / 9;
        int tap = u - pt * 9;
        int b = pt >> 9;
        float px = __ldg(&points[2 * pt + 0]);
        float py = __ldg(&points[2 * pt + 1]);
        int x = (int)fminf(fmaxf(px * SCALE, 0.f), (float)(Wn - 1));
        int y = (int)fminf(fmaxf(py * SCALE, 0.f), (float)(Hn - 1));
        int dy = tap / 3 - 1;
        int dx = tap - (tap / 3) * 3 - 1;
        int ny = y + dy, nx = x + dx;
        bool ok = (unsigned)ny < (unsigned)Hn && (unsigned)nx < (unsigned)Wn;
        size_t idx = (size_t)b * HWn + ny * Wn + nx;

        // ---- dependent: one store ----
        cudaGridDependencySynchronize();
        if (ok) g_target[idx] = 0.f;
        return;
    }

    // finalize block
    cudaGridDependencySynchronize();
    double cnt = 0.0, sp = 0.0;
    if (tid < Bn) {
        double S = g_S[tid];
        cnt = fabs(S / CELL_AREA - (double)NPTS);
        double Sp = S + 1e-8;
        double T = g_T[tid];
        sp = (g_Q[tid] / (Sp * Sp) - 2.0 * g_A[tid] / (Sp * T)
              + g_C[tid] / (T * T)) / (double)HWn;
        g_S[tid] = 0.0; g_Q[tid] = 0.0; g_T[tid] = 0.0;
        g_A[tid] = 0.0; g_C[tid] = 0.0;
    }
    #pragma unroll
    for (int o = 16; o; o >>= 1) {
        cnt += __shfl_down_sync(0xffffffffu, cnt, o);
        sp  += __shfl_down_sync(0xffffffffu, sp, o);
    }
    __shared__ double sc[2], ssp[2];
    int lane = tid & 31, wid = tid >> 5;
    if (wid < 2 && lane == 0) { sc[wid] = cnt; ssp[wid] = sp; }
    __syncthreads();
    if (tid == 0) {
        double count_loss = (sc[0] + sc[1]) / (double)Bn;
        double spatial    = (ssp[0] + ssp[1]) / (double)Bn;
        out[0] = (float)(2.5 * count_loss + 0.1 * spatial);
        out[1] = (float)count_loss;
        out[2] = (float)spatial;
    }
}

extern "C" void kernel_launch(void* const* d_in, const int* in_sizes, int n_in,
                              void* d_out, int out_size) {
    const float* pred   = (const float*)d_in[0];
    const float* points = (const float*)d_in[1];
    float* out = (float*)d_out;

    k_main<<<RB, 256>>>(pred, points);

    cudaLaunchConfig_t cfg = {};
    cfg.gridDim  = dim3(CB + 1);
    cfg.blockDim = dim3(256);
    cudaLaunchAttribute attr[1];
    attr[0].id = cudaLaunchAttributeProgrammaticStreamSerialization;
    attr[0].val.programmaticStreamSerializationAllowed = 1;
    cfg.attrs = attr;
    cfg.numAttrs = 1;
    cudaError_t err = cudaLaunchKernelEx(&cfg, k_tail, points, out);
    if (err != cudaSuccess) {
        k_tail<<<CB + 1, 256>>>(points, out);   // serialized fallback
    }
}

// round 14
// speedup vs baseline: 1.0994x; 1.0994x over previous
#include <cuda_runtime.h>
#include <math.h>

constexpr int Bn   = 64;
constexpr int Hn   = 512;
constexpr int Wn   = 512;
constexpr int NPTS = 512;
constexpr int HWn  = Hn * Wn;
constexpr int SLICES = 16;                  // blocks per image
constexpr int RB = Bn * SLICES;             // 1024 blocks (single wave)
constexpr int TAPS_PER_IMG = NPTS * 9;      // 4608
constexpr int TAPS_PER_BLK = TAPS_PER_IMG / SLICES;   // 288
constexpr int NPR = Bn * NPTS * 3;          // (point,row) pairs = 98304
constexpr int CB = NPR / 256;               // 384 cleanup blocks
constexpr float SCALE = 0.25f;              // 512/2048
constexpr double CELL_AREA = 16.0;

// zero-initialized device scratch; restored every call for graph replay
__device__ float  g_target[(size_t)Bn * HWn];
__device__ double g_S[Bn], g_Q[Bn], g_T[Bn], g_A[Bn], g_C[Bn];

// K1: proven R7/R12 kernel (no early trigger — measured harmful in R13).
__global__ void __launch_bounds__(256, 7)
k_main(const float* __restrict__ pred, const float* __restrict__ points) {
    const int tid = threadIdx.x;
    const int b = blockIdx.x >> 4;
    const int slice = blockIdx.x & (SLICES - 1);

    constexpr int CH = HWn / 4 / SLICES;    // 4096 float4 per block
    const float4* p = reinterpret_cast<const float4*>(pred)
                      + (size_t)b * (HWn / 4) + (size_t)slice * CH;
    float s = 0.f, q = 0.f;
    #pragma unroll
    for (int it = 0; it < 2; ++it) {
        float4 v[8];
        #pragma unroll
        for (int j = 0; j < 8; ++j)
            v[j] = p[(it * 8 + j) * 256 + tid];
        #pragma unroll
        for (int j = 0; j < 8; ++j) {
            s += (v[j].x + v[j].y) + (v[j].z + v[j].w);
            q += v[j].x * v[j].x + v[j].y * v[j].y
               + v[j].z * v[j].z + v[j].w * v[j].w;
        }
    }

    float tw = 0.f, ta = 0.f, tc = 0.f;
    const float* pb = pred + (size_t)b * HWn;
    float* tg = g_target + (size_t)b * HWn;
    for (int i = tid; i < TAPS_PER_BLK; i += 256) {
        int tapid = slice * TAPS_PER_BLK + i;    // < 4608
        int pt  = tapid / 9;
        int tap = tapid - pt * 9;
        float px = __ldg(&points[((size_t)b * NPTS + pt) * 2 + 0]);
        float py = __ldg(&points[((size_t)b * NPTS + pt) * 2 + 1]);
        int x = (int)fminf(fmaxf(px * SCALE, 0.f), (float)(Wn - 1));
        int y = (int)fminf(fmaxf(py * SCALE, 0.f), (float)(Hn - 1));
        int dy = tap / 3 - 1;
        int dx = tap - (tap / 3) * 3 - 1;
        int ny = y + dy, nx = x + dx;
        if ((unsigned)ny < (unsigned)Hn && (unsigned)nx < (unsigned)Wn) {
            int r2 = dy * dy + dx * dx;
            float w = (r2 == 0) ? 1.0f : (r2 == 1 ? 0.60653066f : 0.49306869f);
            int idx = ny * Wn + nx;
            float old = atomicAdd(&tg[idx], w);
            tc += w * (2.f * old + w);            // (old+w)^2 - old^2
            ta += w * __ldg(&pb[idx]);
            tw += w;
        }
    }

    #pragma unroll
    for (int o = 16; o; o >>= 1) {
        s  += __shfl_down_sync(0xffffffffu, s,  o);
        q  += __shfl_down_sync(0xffffffffu, q,  o);
        tw += __shfl_down_sync(0xffffffffu, tw, o);
        ta += __shfl_down_sync(0xffffffffu, ta, o);
        tc += __shfl_down_sync(0xffffffffu, tc, o);
    }
    __shared__ float sh[5][8];
    int lane = tid & 31, wid = tid >> 5;
    if (lane == 0) {
        sh[0][wid] = s; sh[1][wid] = q; sh[2][wid] = tw;
        sh[3][wid] = ta; sh[4][wid] = tc;
    }
    __syncthreads();
    if (tid == 0) {
        float S = 0.f, Q = 0.f, Tw = 0.f, Ta = 0.f, Tc = 0.f;
        #pragma unroll
        for (int j = 0; j < 8; ++j) {
            S += sh[0][j]; Q += sh[1][j]; Tw += sh[2][j];
            Ta += sh[3][j]; Tc += sh[4][j];
        }
        atomicAdd(&g_S[b], (double)S);
        atomicAdd(&g_Q[b], (double)Q);
        atomicAdd(&g_T[b], (double)Tw);
        atomicAdd(&g_A[b], (double)Ta);
        atomicAdd(&g_C[b], (double)Tc);
    }
}

// K2 (PDL): cleanup by (point,row) pair — 3 threads per point, 3 stores each.
// Prologue decodes; gridsync; dependent part = 3 plain stores. Finalize block
// computes the scalar loss.
__global__ void __launch_bounds__(256)
k_tail(const float* __restrict__ points, float* __restrict__ out) {
    const int tid = threadIdx.x;
    if (blockIdx.x < CB) {
        // ---- independent prologue ----
        int u = blockIdx.x * 256 + tid;     // < NPR
        int pt = u / 3;
        int r  = u - pt * 3;                // 0,1,2 -> dy = r-1
        int b  = pt >> 9;
        float px = __ldg(&points[2 * pt + 0]);
        float py = __ldg(&points[2 * pt + 1]);
        int x = (int)fminf(fmaxf(px * SCALE, 0.f), (float)(Wn - 1));
        int y = (int)fminf(fmaxf(py * SCALE, 0.f), (float)(Hn - 1));
        int ny = y + r - 1;
        bool rok = (unsigned)ny < (unsigned)Hn;
        float* row = g_target + (size_t)b * HWn + ny * Wn;
        int x0 = x - 1, x2 = x + 1;
        bool ok0 = rok && x0 >= 0;
        bool ok1 = rok;
        bool ok2 = rok && x2 < Wn;

        // ---- dependent: up to 3 stores ----
        cudaGridDependencySynchronize();
        if (ok0) row[x0] = 0.f;
        if (ok1) row[x]  = 0.f;
        if (ok2) row[x2] = 0.f;
        return;
    }

    // finalize block
    cudaGridDependencySynchronize();
    double cnt = 0.0, sp = 0.0;
    if (tid < Bn) {
        double S = g_S[tid];
        cnt = fabs(S / CELL_AREA - (double)NPTS);
        double Sp = S + 1e-8;
        double T = g_T[tid];
        sp = (g_Q[tid] / (Sp * Sp) - 2.0 * g_A[tid] / (Sp * T)
              + g_C[tid] / (T * T)) / (double)HWn;
        g_S[tid] = 0.0; g_Q[tid] = 0.0; g_T[tid] = 0.0;
        g_A[tid] = 0.0; g_C[tid] = 0.0;
    }
    #pragma unroll
    for (int o = 16; o; o >>= 1) {
        cnt += __shfl_down_sync(0xffffffffu, cnt, o);
        sp  += __shfl_down_sync(0xffffffffu, sp, o);
    }
    __shared__ double sc[2], ssp[2];
    int lane = tid & 31, wid = tid >> 5;
    if (wid < 2 && lane == 0) { sc[wid] = cnt; ssp[wid] = sp; }
    __syncthreads();
    if (tid == 0) {
        double count_loss = (sc[0] + sc[1]) / (double)Bn;
        double spatial    = (ssp[0] + ssp[1]) / (double)Bn;
        out[0] = (float)(2.5 * count_loss + 0.1 * spatial);
        out[1] = (float)count_loss;
        out[2] = (float)spatial;
    }
}

extern "C" void kernel_launch(void* const* d_in, const int* in_sizes, int n_in,
                              void* d_out, int out_size) {
    const float* pred   = (const float*)d_in[0];
    const float* points = (const float*)d_in[1];
    float* out = (float*)d_out;

    k_main<<<RB, 256>>>(pred, points);

    cudaLaunchConfig_t cfg = {};
    cfg.gridDim  = dim3(CB + 1);
    cfg.blockDim = dim3(256);
    cudaLaunchAttribute attr[1];
    attr[0].id = cudaLaunchAttributeProgrammaticStreamSerialization;
    attr[0].val.programmaticStreamSerializationAllowed = 1;
    cfg.attrs = attr;
    cfg.numAttrs = 1;
    cudaError_t err = cudaLaunchKernelEx(&cfg, k_tail, points, out);
    if (err != cudaSuccess) {
        k_tail<<<CB + 1, 256>>>(points, out);   // serialized fallback
    }
}